// round 14
// baseline (speedup 1.0000x reference)
#include <cuda_runtime.h>
#include <cuda_fp16.h>
#include <stdint.h>

// Problem constants
#define NN   20000
#define EE   640000
#define FIN  128
#define FOUT 128
#define RR   65
#define BB   65
#define TILE_M 128
#define NBN  200

#define ROWB 272                  // bytes per smem B row (136 halves, padded)
#define BTILE (128 * ROWB)        // 34816 B
#define GEMM_GRID 296
#define NTSYN ((NN + TILE_M - 1) / TILE_M)   // synthetic residual tiles (157)

// ---------------- scratch (__device__ globals) ------------------------------
__device__ __align__(16) __half g_WT[(size_t)(RR + 1) * FOUT * FIN]; // [r][o][k]; slot RR = W_res
__device__ __align__(16) __half g_xh[(size_t)NN * FIN];
__device__ int   g_cnt[RR];
__device__ int   g_rcur[RR];
__device__ int   g_estart[RR + 1];
__device__ int   g_tstart[RR + 2];               // [RR+1] = total incl synthetic
__device__ int   g_perm[EE];
__device__ int   g_dcnt[NN];
__device__ int   g_dcur[NN];
__device__ int   g_dstart[NN + 1];
__device__ int   g_bsum[20];
__device__ int   g_boff[20];
__device__ int   g_dinv[EE];                     // edge -> dst-sorted rank
__device__ __align__(16) __half g_edge_out[(size_t)(EE + NN) * FOUT]; // + residual rows
__device__ float g_h[(size_t)NN * FOUT];
__device__ float g_psum[NBN * FOUT];
__device__ float g_psq[NBN * FOUT];
__device__ float g_scale[FOUT];
__device__ float g_shift[FOUT];

// ---------------- helpers ----------------------------------------------------
__device__ __forceinline__ uint32_t smem_u32(const void* p) {
    uint32_t a;
    asm("{ .reg .u64 t; cvta.to.shared.u64 t, %1; cvt.u32.u64 %0, t; }"
        : "=r"(a) : "l"(p));
    return a;
}

__device__ __forceinline__ void ldsm_x4(uint32_t addr, uint32_t& r0, uint32_t& r1,
                                        uint32_t& r2, uint32_t& r3) {
    asm volatile("ldmatrix.sync.aligned.m8n8.x4.shared.b16 {%0,%1,%2,%3}, [%4];"
                 : "=r"(r0), "=r"(r1), "=r"(r2), "=r"(r3) : "r"(addr));
}

// fp16-accumulator HMMA
__device__ __forceinline__ void mma16816h(uint32_t* c, const uint32_t* a,
                                          uint32_t b0, uint32_t b1) {
    asm volatile(
        "mma.sync.aligned.m16n8k16.row.col.f16.f16.f16.f16 "
        "{%0,%1}, {%2,%3,%4,%5}, {%6,%7}, {%0,%1};"
        : "+r"(c[0]), "+r"(c[1])
        : "r"(a[0]), "r"(a[1]), "r"(a[2]), "r"(a[3]), "r"(b0), "r"(b1));
}

__device__ __forceinline__ void cp16(uint32_t dst, const void* src) {
    asm volatile("cp.async.cg.shared.global [%0], [%1], 16;"
                 :: "r"(dst), "l"(src) : "memory");
}
#define CP_COMMIT() asm volatile("cp.async.commit_group;" ::: "memory")
#define CP_WAIT0()  asm volatile("cp.async.wait_group 0;" ::: "memory")

// ---------------- K1: WT fp16 (+ zero counters) ---------------------------------
__global__ __launch_bounds__(128) void k_w(const float* __restrict__ basis,
                                           const float* __restrict__ comp) {
    extern __shared__ float swm[];
    float* sb = swm;              // [BB][FIN] = basis[b][i][o] for fixed i
    float* sc = swm + BB * FIN;   // [RR*BB]

    int i = blockIdx.x, o = threadIdx.x;

    // fold in counter zeroing (16384 threads total)
    int gi = blockIdx.x * 128 + o;
    for (int z = gi; z < NN; z += FIN * 128) { g_dcnt[z] = 0; g_dcur[z] = 0; }
    if (gi < RR) { g_cnt[gi] = 0; g_rcur[gi] = 0; }

    for (int b = 0; b < BB; b++)
        sb[b * FIN + o] = basis[(size_t)b * FIN * FOUT + (size_t)i * FOUT + o];
    for (int idx = o; idx < RR * BB; idx += 128)
        sc[idx] = comp[idx];
    __syncthreads();

    float acc[RR];
    #pragma unroll
    for (int r = 0; r < RR; r++) acc[r] = 0.f;

    for (int b = 0; b < BB; b++) {
        float sv = sb[b * FIN + o];
        #pragma unroll
        for (int r = 0; r < RR; r++)
            acc[r] += sc[r * BB + b] * sv;
    }

    #pragma unroll 1
    for (int r = 0; r < RR; r++)
        g_WT[((size_t)r * FOUT + o) * FIN + i] = __float2half(acc[r]);
}

// ---------------- K2: merged preprocessing ---------------------------------------
__global__ void k_pre(const float* __restrict__ x,
                      const int* __restrict__ etype,
                      const int* __restrict__ dst,
                      const float* __restrict__ Wres) {
    __shared__ int sh[RR];
    int tid = threadIdx.x;
    int gb = blockIdx.x;
    int i = gb * 256 + tid;

    if (i < NN * FIN / 2) {
        float2 v = ((const float2*)x)[i];
        ((__half2*)g_xh)[i] = __floats2half2_rn(v.x, v.y);
    }
    if (i < FIN * FOUT) {
        int k = i >> 7, o = i & 127;
        g_WT[((size_t)RR * FOUT + o) * FIN + k] = __float2half(Wres[i]);
    }
    if (gb < (EE + 255) / 256) {
        if (tid < RR) sh[tid] = 0;
        __syncthreads();
        if (i < EE) {
            atomicAdd(&sh[etype[i]], 1);
            atomicAdd(&g_dcnt[dst[i]], 1);
        }
        __syncthreads();
        if (tid < RR && sh[tid]) atomicAdd(&g_cnt[tid], sh[tid]);
    }
}

// ---------------- K3a: local scans (20 blocks x 1000 counts) --------------------
__global__ __launch_bounds__(1024) void k_scan1() {
    __shared__ int sa[1024], sb2[1024];
    int t = threadIdx.x;
    int g = blockIdx.x * 1000;
    int v = (t < 1000) ? g_dcnt[g + t] : 0;
    sa[t] = v;
    __syncthreads();
    int* in = sa; int* out = sb2;
    #pragma unroll
    for (int off = 1; off < 1024; off <<= 1) {
        out[t] = in[t] + ((t >= off) ? in[t - off] : 0);
        __syncthreads();
        int* tmp = in; in = out; out = tmp;
    }
    if (t < 1000) g_dstart[g + t] = in[t] - v;      // local exclusive
    if (t == 999) g_bsum[blockIdx.x] = in[t];       // block total
}

// ---------------- K3b: block offsets + relation scan ------------------------------
__global__ void k_scan2() {
    if (threadIdx.x == 0) {
        int run = 0;
        for (int k = 0; k < 20; k++) { g_boff[k] = run; run += g_bsum[k]; }
        g_dstart[NN] = run;
        int es = 0, ts = 0;
        for (int r = 0; r < RR; r++) {
            g_estart[r] = es; g_tstart[r] = ts;
            es += g_cnt[r];
            ts += (g_cnt[r] + TILE_M - 1) / TILE_M;
        }
        g_estart[RR] = es;
        g_tstart[RR] = ts;
        g_tstart[RR + 1] = ts + NTSYN;
    }
}

// ---------------- K3c: add block offsets -------------------------------------------
__global__ __launch_bounds__(1024) void k_scan3() {
    int t = threadIdx.x;
    if (t < 1000) g_dstart[blockIdx.x * 1000 + t] += g_boff[blockIdx.x];
}

// ---------------- K4: scatter ------------------------------------------------------
__global__ void k_scatter(const int* __restrict__ etype, const int* __restrict__ dst) {
    __shared__ int s_cnt[RR], s_base[RR];
    int tid = threadIdx.x;
    if (tid < RR) s_cnt[tid] = 0;
    __syncthreads();
    int e = blockIdx.x * 256 + tid;
    bool valid = (e < EE);
    int r = 0, lrank = 0;
    if (valid) { r = etype[e]; lrank = atomicAdd(&s_cnt[r], 1); }
    __syncthreads();
    if (tid < RR && s_cnt[tid] > 0) s_base[tid] = atomicAdd(&g_rcur[tid], s_cnt[tid]);
    __syncthreads();
    if (valid) {
        g_perm[g_estart[r] + s_base[r] + lrank] = e;
        int d = dst[e];
        g_dinv[e] = g_dstart[d] + atomicAdd(&g_dcur[d], 1);
    }
}

// ---------------- K5: persistent HMMA GEMM, A direct-from-L2 ---------------------
// smem: B tile only (34816 B). Each thread privately owns 4 output rows
// (its mma fragment rows) — loads A frags via LDG.32, no A staging, no per-tile
// syncs. Sync only at relation changes (B reload).
__global__ __launch_bounds__(256, 2) void k_gemm(const int* __restrict__ src,
                                                 const float* __restrict__ norm) {
    extern __shared__ char dsm[];
    char* B = dsm;

    int tid = threadIdx.x;
    int T = g_tstart[RR + 1];
    int per = (T + GEMM_GRID - 1) / GEMM_GRID;
    int t0 = blockIdx.x * per;
    int t1 = t0 + per; if (t1 > T) t1 = T;
    if (t0 >= t1) return;

    int lane = tid & 31, w = tid >> 5;
    int wm = w & 3, wn = w >> 2;            // 4 M-groups x 2 N-groups
    int rm = wm * 32;
    int g = lane >> 2, tg = lane & 3;

    uint32_t bLane = (uint32_t)((wn * 64 + ((lane >> 4) << 3) + (lane & 7)) * ROWB
                                + (((lane >> 3) & 1) << 4));
    uint32_t bAddr = smem_u32(B) + bLane;

    // this thread's 4 rows within the tile (mma fragment rows)
    int rowIdx[4] = { rm + g, rm + g + 8, rm + 16 + g, rm + 24 + g };

    int r = 0;
    while (g_tstart[r + 1] <= t0) r++;

    // ---- B fill for first relation ----
    {
        const char* WB = (const char*)g_WT + (size_t)r * 32768;
        #pragma unroll
        for (int it = 0; it < 8; it++) {
            int id = tid + it * 256;
            int o = id >> 4, j = id & 15;
            cp16(smem_u32(B + o * ROWB + j * 16), WB + o * 256 + j * 16);
        }
        CP_COMMIT();
    }
    CP_WAIT0();
    __syncthreads();

    for (int t = t0; t < t1; t++) {
        // ---- per-thread meta for its 4 rows ----
        const char* xp[4];
        int   dv[4];
        float nm[4];
        if (r < RR) {
            int ebase = g_estart[r] + (t - g_tstart[r]) * TILE_M;
            int eend = g_estart[r + 1];
            #pragma unroll
            for (int q = 0; q < 4; q++) {
                int epos = ebase + rowIdx[q];
                int sv = 0; dv[q] = -1; nm[q] = 0.f;
                if (epos < eend) {
                    int e = __ldg(&g_perm[epos]);
                    sv = __ldg(&src[e]); nm[q] = __ldg(&norm[e]); dv[q] = __ldg(&g_dinv[e]);
                }
                xp[q] = (const char*)g_xh + (size_t)sv * 256 + tg * 4;
            }
        } else {
            int nbase = (t - g_tstart[RR]) * TILE_M;
            #pragma unroll
            for (int q = 0; q < 4; q++) {
                int n = nbase + rowIdx[q];
                int sv = 0; dv[q] = -1; nm[q] = 0.f;
                if (n < NN) { sv = n; nm[q] = 1.f; dv[q] = EE + n; }
                xp[q] = (const char*)g_xh + (size_t)sv * 256 + tg * 4;
            }
        }

        // fp16 accumulators: [mt][nt][row-half]
        uint32_t acc[2][8][2];
        #pragma unroll
        for (int a = 0; a < 2; a++)
            #pragma unroll
            for (int b = 0; b < 8; b++) { acc[a][b][0] = 0u; acc[a][b][1] = 0u; }

        // A-register double buffer: [buf][mt*4 + frag]
        uint32_t Ar[2][8];
        #pragma unroll
        for (int q = 0; q < 2; q++) {
            // frag order per mt: a0(row g,c), a1(row g+8,c), a2(row g,c+8), a3(row g+8,c+8)
            Ar[0][q * 4 + 0] = __ldg((const uint32_t*)(xp[q * 2 + 0]));
            Ar[0][q * 4 + 1] = __ldg((const uint32_t*)(xp[q * 2 + 1]));
            Ar[0][q * 4 + 2] = __ldg((const uint32_t*)(xp[q * 2 + 0] + 16));
            Ar[0][q * 4 + 3] = __ldg((const uint32_t*)(xp[q * 2 + 1] + 16));
        }

        #pragma unroll
        for (int s = 0; s < 8; s++) {
            int cur = s & 1, nxt = cur ^ 1;
            if (s < 7) {
                int off = (s + 1) * 32;
                #pragma unroll
                for (int q = 0; q < 2; q++) {
                    Ar[nxt][q * 4 + 0] = __ldg((const uint32_t*)(xp[q * 2 + 0] + off));
                    Ar[nxt][q * 4 + 1] = __ldg((const uint32_t*)(xp[q * 2 + 1] + off));
                    Ar[nxt][q * 4 + 2] = __ldg((const uint32_t*)(xp[q * 2 + 0] + off + 16));
                    Ar[nxt][q * 4 + 3] = __ldg((const uint32_t*)(xp[q * 2 + 1] + off + 16));
                }
            }
            uint32_t kb = bAddr + s * 32;
            #pragma unroll
            for (int pr = 0; pr < 4; pr++) {
                uint32_t b0, b1, b2, b3;
                ldsm_x4(kb + pr * 16 * ROWB, b0, b1, b2, b3);
                int nt = pr * 2;
                mma16816h(acc[0][nt],     &Ar[cur][0], b0, b1);
                mma16816h(acc[1][nt],     &Ar[cur][4], b0, b1);
                mma16816h(acc[0][nt + 1], &Ar[cur][0], b2, b3);
                mma16816h(acc[1][nt + 1], &Ar[cur][4], b2, b3);
            }
        }

        // ---- epilogue: scale by norm in fp32, store half2 at dst-rank ----
        {
            int colBase = wn * 64 + tg * 2;
            #pragma unroll
            for (int mt = 0; mt < 2; mt++) {
                int d0 = dv[mt * 2], d1 = dv[mt * 2 + 1];
                float n0 = nm[mt * 2], n1 = nm[mt * 2 + 1];
                __half* p0 = (d0 >= 0) ? g_edge_out + (size_t)d0 * FOUT + colBase : (__half*)0;
                __half* p1 = (d1 >= 0) ? g_edge_out + (size_t)d1 * FOUT + colBase : (__half*)0;
                #pragma unroll
                for (int nt = 0; nt < 8; nt++) {
                    if (p0) {
                        uint32_t v = acc[mt][nt][0];
                        float2 f = __half22float2(*(__half2*)&v);
                        *(__half2*)(p0 + nt * 8) = __floats2half2_rn(f.x * n0, f.y * n0);
                    }
                    if (p1) {
                        uint32_t v = acc[mt][nt][1];
                        float2 f = __half22float2(*(__half2*)&v);
                        *(__half2*)(p1 + nt * 8) = __floats2half2_rn(f.x * n1, f.y * n1);
                    }
                }
            }
        }

        // ---- B reload on relation change (rare; aligned across all warps) ----
        if (t + 1 < t1 && g_tstart[r + 1] <= t + 1) {
            int rn = r;
            while (g_tstart[rn + 1] <= t + 1) rn++;
            __syncthreads();   // all warps done reading old B
            const char* WB = (const char*)g_WT + (size_t)rn * 32768;
            #pragma unroll
            for (int it = 0; it < 8; it++) {
                int id = tid + it * 256;
                int o = id >> 4, j = id & 15;
                cp16(smem_u32(B + o * ROWB + j * 16), WB + o * 256 + j * 16);
            }
            CP_COMMIT();
            CP_WAIT0();
            __syncthreads();
            r = rn;
        }
    }
}

// ---------------- K6: warp-per-node reduce + bias/relu + residual bias/relu ------
__global__ __launch_bounds__(256) void k_reduce(const float* __restrict__ h_bias,
                                                const float* __restrict__ b_res) {
    int n = (blockIdx.x << 3) + (threadIdx.x >> 5);
    int lane = threadIdx.x & 31;
    int h = lane >> 4;
    int c = lane & 15;

    int s = g_dstart[n], e = g_dstart[n + 1];
    float2 a0 = make_float2(0.f, 0.f), a1 = a0, a2 = a0, a3 = a0;

    const uint4* base = (const uint4*)g_edge_out;
    for (int j = s + h; j < e; j += 2) {
        uint4 v = base[(size_t)j * 16 + c];
        float2 f;
        f = __half22float2(*(__half2*)&v.x); a0.x += f.x; a0.y += f.y;
        f = __half22float2(*(__half2*)&v.y); a1.x += f.x; a1.y += f.y;
        f = __half22float2(*(__half2*)&v.z); a2.x += f.x; a2.y += f.y;
        f = __half22float2(*(__half2*)&v.w); a3.x += f.x; a3.y += f.y;
    }
    a0.x += __shfl_down_sync(0xffffffffu, a0.x, 16);
    a0.y += __shfl_down_sync(0xffffffffu, a0.y, 16);
    a1.x += __shfl_down_sync(0xffffffffu, a1.x, 16);
    a1.y += __shfl_down_sync(0xffffffffu, a1.y, 16);
    a2.x += __shfl_down_sync(0xffffffffu, a2.x, 16);
    a2.y += __shfl_down_sync(0xffffffffu, a2.y, 16);
    a3.x += __shfl_down_sync(0xffffffffu, a3.x, 16);
    a3.y += __shfl_down_sync(0xffffffffu, a3.y, 16);

    if (h == 0) {
        const float4* bia = (const float4*)h_bias;
        float4 b0 = __ldg(&bia[c * 2]), b1 = __ldg(&bia[c * 2 + 1]);
        uint4 rv = base[(size_t)(EE + n) * 16 + c];
        float2 rf0 = __half22float2(*(__half2*)&rv.x);
        float2 rf1 = __half22float2(*(__half2*)&rv.y);
        float2 rf2 = __half22float2(*(__half2*)&rv.z);
        float2 rf3 = __half22float2(*(__half2*)&rv.w);
        const float4* brp = (const float4*)b_res;
        float4 br0 = __ldg(&brp[c * 2]), br1 = __ldg(&brp[c * 2 + 1]);

        float4 o0, o1;
        o0.x = fmaxf(a0.x + b0.x, 0.f) + fmaxf(rf0.x + br0.x, 0.f);
        o0.y = fmaxf(a0.y + b0.y, 0.f) + fmaxf(rf0.y + br0.y, 0.f);
        o0.z = fmaxf(a1.x + b0.z, 0.f) + fmaxf(rf1.x + br0.z, 0.f);
        o0.w = fmaxf(a1.y + b0.w, 0.f) + fmaxf(rf1.y + br0.w, 0.f);
        o1.x = fmaxf(a2.x + b1.x, 0.f) + fmaxf(rf2.x + br1.x, 0.f);
        o1.y = fmaxf(a2.y + b1.y, 0.f) + fmaxf(rf2.y + br1.y, 0.f);
        o1.z = fmaxf(a3.x + b1.z, 0.f) + fmaxf(rf3.x + br1.z, 0.f);
        o1.w = fmaxf(a3.y + b1.w, 0.f) + fmaxf(rf3.y + br1.w, 0.f);
        ((float4*)g_h)[(size_t)n * 32 + c * 2]     = o0;
        ((float4*)g_h)[(size_t)n * 32 + c * 2 + 1] = o1;
    }
}

// ---------------- K7/K8/K9: BN -----------------------------------------------------
__global__ __launch_bounds__(128) void k_bnsum() {
    int b = blockIdx.x, o = threadIdx.x;
    float s = 0.f, sq = 0.f;
    int r0 = b * (NN / NBN), r1 = r0 + (NN / NBN);
    for (int n = r0; n < r1; n++) {
        float v = g_h[(size_t)n * FOUT + o];
        s += v; sq += v * v;
    }
    g_psum[b * FOUT + o] = s;
    g_psq[b * FOUT + o] = sq;
}

__global__ __launch_bounds__(128) void k_bnfin(const float* __restrict__ gamma,
                                               const float* __restrict__ beta) {
    int o = threadIdx.x;
    float s = 0.f, sq = 0.f;
    for (int b = 0; b < NBN; b++) { s += g_psum[b * FOUT + o]; sq += g_psq[b * FOUT + o]; }
    float mean = s / (float)NN;
    float var = sq / (float)NN - mean * mean;
    float sc = gamma[o] * rsqrtf(var + 1e-5f);
    g_scale[o] = sc;
    g_shift[o] = beta[o] - mean * sc;
}

__global__ void k_out(float* __restrict__ out) {
    int i = blockIdx.x * 256 + threadIdx.x;          // float4 index
    if (i < NN * FOUT / 4) {
        float4 v = ((const float4*)g_h)[i];
        int c4 = i & 31;
        float4 sc = ((const float4*)g_scale)[c4];
        float4 sh = ((const float4*)g_shift)[c4];
        float4 o;
        o.x = v.x * sc.x + sh.x;
        o.y = v.y * sc.y + sh.y;
        o.z = v.z * sc.z + sh.z;
        o.w = v.w * sc.w + sh.w;
        ((float4*)out)[i] = o;
    }
}

// ---------------- launch -------------------------------------------------------------
extern "C" void kernel_launch(void* const* d_in, const int* in_sizes, int n_in,
                              void* d_out, int out_size) {
    const float* node_feats = (const float*)d_in[0];
    const int*   src        = (const int*)d_in[1];
    const int*   dst        = (const int*)d_in[2];
    const int*   etype      = (const int*)d_in[3];
    const float* norm       = (const float*)d_in[4];
    const float* basis      = (const float*)d_in[5];
    const float* comp       = (const float*)d_in[6];
    const float* h_bias     = (const float*)d_in[7];
    const float* W_res      = (const float*)d_in[8];
    const float* b_res      = (const float*)d_in[9];
    const float* gamma      = (const float*)d_in[10];
    const float* beta       = (const float*)d_in[11];
    float* out = (float*)d_out;

    const int DSMEM   = BTILE;                          // 34816 B
    const int KW_SMEM = (BB * FIN + RR * BB) * 4;       // 50180 B
    cudaFuncSetAttribute(k_gemm, cudaFuncAttributeMaxDynamicSharedMemorySize, DSMEM);
    cudaFuncSetAttribute(k_w, cudaFuncAttributeMaxDynamicSharedMemorySize, KW_SMEM);

    k_w<<<FIN, 128, KW_SMEM>>>(basis, comp);
    k_pre<<<(NN * FIN / 2 + 255) / 256, 256>>>(node_feats, etype, dst, W_res);
    k_scan1<<<20, 1024>>>();
    k_scan2<<<1, 32>>>();
    k_scan3<<<20, 1024>>>();
    k_scatter<<<(EE + 255) / 256, 256>>>(etype, dst);
    k_gemm<<<GEMM_GRID, 256, DSMEM>>>(src, norm);
    k_reduce<<<NN / 8, 256>>>(h_bias, b_res);
    k_bnsum<<<NBN, 128>>>();
    k_bnfin<<<1, 128>>>(gamma, beta);
    k_out<<<(NN * FOUT / 4 + 255) / 256, 256>>>(out);
    (void)in_sizes; (void)n_in; (void)out_size;
}

// round 15
// speedup vs baseline: 1.2068x; 1.2068x over previous
#include <cuda_runtime.h>
#include <cuda_fp16.h>
#include <stdint.h>

// Problem constants
#define NN   20000
#define EE   640000
#define FIN  128
#define FOUT 128
#define RR   65
#define BB   65
#define TILE_M 128
#define NBN  200

#define ROWB 272                  // bytes per smem tile row (136 halves, padded)
#define ATILE (128 * ROWB)        // 34816 B
#define GEMM_GRID 444             // 3 CTAs per SM
#define NTSYN ((NN + TILE_M - 1) / TILE_M)   // synthetic residual tiles (157)

// ---------------- scratch (__device__ globals) ------------------------------
__device__ __align__(16) __half g_WT[(size_t)(RR + 1) * FOUT * FIN]; // slot RR = W_res
__device__ __align__(16) __half g_xh[(size_t)NN * FIN];
__device__ int   g_cnt[RR];
__device__ int   g_rcur[RR];
__device__ int   g_estart[RR + 1];
__device__ int   g_tstart[RR + 2];
__device__ int   g_perm[EE];
__device__ int   g_dcnt[NN];
__device__ int   g_dcur[NN];
__device__ int   g_dstart[NN];                   // LOCAL exclusive (per 1000-chunk)
__device__ int   g_bsum[20];
__device__ int   g_dinv[EE];                     // edge -> dst-sorted rank
__device__ __align__(16) __half g_edge_out[(size_t)(EE + NN) * FOUT];
__device__ float g_h[(size_t)NN * FOUT];
__device__ float g_psum[NBN * FOUT];
__device__ float g_psq[NBN * FOUT];

// ---------------- helpers ----------------------------------------------------
__device__ __forceinline__ uint32_t smem_u32(const void* p) {
    uint32_t a;
    asm("{ .reg .u64 t; cvta.to.shared.u64 t, %1; cvt.u32.u64 %0, t; }"
        : "=r"(a) : "l"(p));
    return a;
}

__device__ __forceinline__ void ldsm_x4(uint32_t addr, uint32_t& r0, uint32_t& r1,
                                        uint32_t& r2, uint32_t& r3) {
    asm volatile("ldmatrix.sync.aligned.m8n8.x4.shared.b16 {%0,%1,%2,%3}, [%4];"
                 : "=r"(r0), "=r"(r1), "=r"(r2), "=r"(r3) : "r"(addr));
}

__device__ __forceinline__ void mma16816h(uint32_t* c, const uint32_t* a,
                                          uint32_t b0, uint32_t b1) {
    asm volatile(
        "mma.sync.aligned.m16n8k16.row.col.f16.f16.f16.f16 "
        "{%0,%1}, {%2,%3,%4,%5}, {%6,%7}, {%0,%1};"
        : "+r"(c[0]), "+r"(c[1])
        : "r"(a[0]), "r"(a[1]), "r"(a[2]), "r"(a[3]), "r"(b0), "r"(b1));
}

__device__ __forceinline__ void cp16(uint32_t dst, const void* src) {
    asm volatile("cp.async.cg.shared.global [%0], [%1], 16;"
                 :: "r"(dst), "l"(src) : "memory");
}
#define CP_COMMIT() asm volatile("cp.async.commit_group;" ::: "memory")
#define CP_WAIT0()  asm volatile("cp.async.wait_group 0;" ::: "memory")

// ---------------- K1: WT fp16 (+ zero counters) ---------------------------------
__global__ __launch_bounds__(128) void k_w(const float* __restrict__ basis,
                                           const float* __restrict__ comp) {
    extern __shared__ float swm[];
    float* sb = swm;              // [BB][FIN]
    float* sc = swm + BB * FIN;   // [RR*BB]

    int i = blockIdx.x, o = threadIdx.x;

    int gi = blockIdx.x * 128 + o;
    for (int z = gi; z < NN; z += FIN * 128) { g_dcnt[z] = 0; g_dcur[z] = 0; }
    if (gi < RR) { g_cnt[gi] = 0; g_rcur[gi] = 0; }

    for (int b = 0; b < BB; b++)
        sb[b * FIN + o] = basis[(size_t)b * FIN * FOUT + (size_t)i * FOUT + o];
    for (int idx = o; idx < RR * BB; idx += 128)
        sc[idx] = comp[idx];
    __syncthreads();

    float acc[RR];
    #pragma unroll
    for (int r = 0; r < RR; r++) acc[r] = 0.f;

    for (int b = 0; b < BB; b++) {
        float sv = sb[b * FIN + o];
        #pragma unroll
        for (int r = 0; r < RR; r++)
            acc[r] += sc[r * BB + b] * sv;
    }

    #pragma unroll 1
    for (int r = 0; r < RR; r++)
        g_WT[((size_t)r * FOUT + o) * FIN + i] = __float2half(acc[r]);
}

// ---------------- K2: merged preprocessing ---------------------------------------
__global__ void k_pre(const float* __restrict__ x,
                      const int* __restrict__ etype,
                      const int* __restrict__ dst,
                      const float* __restrict__ Wres) {
    __shared__ int sh[RR];
    int tid = threadIdx.x;
    int gb = blockIdx.x;
    int i = gb * 256 + tid;

    if (i < NN * FIN / 2) {
        float2 v = ((const float2*)x)[i];
        ((__half2*)g_xh)[i] = __floats2half2_rn(v.x, v.y);
    }
    if (i < FIN * FOUT) {
        int k = i >> 7, o = i & 127;
        g_WT[((size_t)RR * FOUT + o) * FIN + k] = __float2half(Wres[i]);
    }
    if (gb < (EE + 255) / 256) {
        if (tid < RR) sh[tid] = 0;
        __syncthreads();
        if (i < EE) {
            atomicAdd(&sh[etype[i]], 1);
            atomicAdd(&g_dcnt[dst[i]], 1);
        }
        __syncthreads();
        if (tid < RR && sh[tid]) atomicAdd(&g_cnt[tid], sh[tid]);
    }
}

// ---------------- K3: local dst scans (blocks 0-19) + relation scan (block 20) ----
__global__ __launch_bounds__(1024) void k_scan1() {
    if (blockIdx.x == 20) {
        if (threadIdx.x == 0) {
            int es = 0, ts = 0;
            for (int r = 0; r < RR; r++) {
                g_estart[r] = es; g_tstart[r] = ts;
                es += g_cnt[r];
                ts += (g_cnt[r] + TILE_M - 1) / TILE_M;
            }
            g_estart[RR] = es;
            g_tstart[RR] = ts;
            g_tstart[RR + 1] = ts + NTSYN;
        }
        return;
    }
    __shared__ int sa[1024], sb2[1024];
    int t = threadIdx.x;
    int g = blockIdx.x * 1000;
    int v = (t < 1000) ? g_dcnt[g + t] : 0;
    sa[t] = v;
    __syncthreads();
    int* in = sa; int* out = sb2;
    #pragma unroll
    for (int off = 1; off < 1024; off <<= 1) {
        out[t] = in[t] + ((t >= off) ? in[t - off] : 0);
        __syncthreads();
        int* tmp = in; in = out; out = tmp;
    }
    if (t < 1000) g_dstart[g + t] = in[t] - v;      // local exclusive
    if (t == 999) g_bsum[blockIdx.x] = in[t];       // block total
}

// ---------------- K4: scatter (boff applied inline) -------------------------------
__global__ void k_scatter(const int* __restrict__ etype, const int* __restrict__ dst) {
    __shared__ int s_cnt[RR], s_base[RR], sboff[20];
    int tid = threadIdx.x;
    if (tid < RR) s_cnt[tid] = 0;
    if (tid >= 64 && tid < 84) sboff[tid - 64] = g_bsum[tid - 64];
    __syncthreads();
    if (tid == 0) {
        int run = 0;
        #pragma unroll
        for (int k = 0; k < 20; k++) { int v = sboff[k]; sboff[k] = run; run += v; }
    }
    __syncthreads();
    int e = blockIdx.x * 256 + tid;
    bool valid = (e < EE);
    int r = 0, lrank = 0;
    if (valid) { r = etype[e]; lrank = atomicAdd(&s_cnt[r], 1); }
    __syncthreads();
    if (tid < RR && s_cnt[tid] > 0) s_base[tid] = atomicAdd(&g_rcur[tid], s_cnt[tid]);
    __syncthreads();
    if (valid) {
        g_perm[g_estart[r] + s_base[r] + lrank] = e;
        int d = dst[e];
        g_dinv[e] = g_dstart[d] + sboff[d / 1000] + atomicAdd(&g_dcur[d], 1);
    }
}

// single-product k-step, fp16 accumulators
#define KSTEP(S, aA) do { \
    uint32_t ka = (aA) + (S) * 32; \
    uint32_t a0[4], a1[4]; \
    ldsm_x4(ka,             a0[0], a0[1], a0[2], a0[3]); \
    ldsm_x4(ka + 16 * ROWB, a1[0], a1[1], a1[2], a1[3]); \
    uint32_t kb = bAddr + (S) * 32; \
    _Pragma("unroll") \
    for (int pr = 0; pr < 4; pr++) { \
        uint32_t b0, b1, b2, b3; \
        ldsm_x4(kb + pr * 16 * ROWB, b0, b1, b2, b3); \
        int nt = pr * 2; \
        mma16816h(acc[0][nt],     a0, b0, b1); \
        mma16816h(acc[1][nt],     a1, b0, b1); \
        mma16816h(acc[0][nt + 1], a0, b2, b3); \
        mma16816h(acc[1][nt + 1], a1, b2, b3); \
    } \
} while (0)

// ---------------- K5: persistent HMMA GEMM, single A buffer, 3 CTAs/SM ------------
__global__ __launch_bounds__(256, 3) void k_gemm(const int* __restrict__ src,
                                                 const float* __restrict__ norm) {
    extern __shared__ char dsm[];
    __shared__ int   s_src[2][TILE_M];
    __shared__ float s_nrm[2][TILE_M];
    __shared__ int   s_dinv[2][TILE_M];

    char* A = dsm;
    char* B = dsm + ATILE;

    int tid = threadIdx.x;
    int T = g_tstart[RR + 1];
    int per = (T + GEMM_GRID - 1) / GEMM_GRID;
    int t0 = blockIdx.x * per;
    int t1 = t0 + per; if (t1 > T) t1 = T;
    if (t0 >= t1) return;

    int lane = tid & 31, w = tid >> 5;
    int wm = w & 3, wn = w >> 2;
    int rm = wm * 32;
    uint32_t aLane = (uint32_t)((rm + (lane & 15)) * ROWB + ((lane >> 4) << 4));
    uint32_t bLane = (uint32_t)((wn * 64 + ((lane >> 4) << 3) + (lane & 7)) * ROWB
                                + (((lane >> 3) & 1) << 4));
    uint32_t aAddr = smem_u32(A) + aLane;
    uint32_t bAddr = smem_u32(B) + bLane;

    int r = 0;
    while (g_tstart[r + 1] <= t0) r++;

    // ---- meta for tile t0 (buf 0) ----
    if (tid < TILE_M) {
        int sv = 0, dv = -1; float nm = 0.f;
        if (r < RR) {
            int ebase = g_estart[r] + (t0 - g_tstart[r]) * TILE_M;
            int cnt = g_estart[r + 1] - ebase; if (cnt > TILE_M) cnt = TILE_M;
            if (tid < cnt) {
                int e = g_perm[ebase + tid];
                sv = src[e]; nm = norm[e]; dv = g_dinv[e];
            }
        } else {
            int n = (t0 - g_tstart[RR]) * TILE_M + tid;
            if (n < NN) { sv = n; nm = 1.f; dv = EE + n; }
        }
        s_src[0][tid] = sv; s_nrm[0][tid] = nm; s_dinv[0][tid] = dv;
    }
    __syncthreads();

    // ---- B fill for first relation + A fill for t0 (committed; waited at loop top)
    {
        const char* WB = (const char*)g_WT + (size_t)r * 32768;
        #pragma unroll
        for (int it = 0; it < 8; it++) {
            int id = tid + it * 256;
            int o = id >> 4, j = id & 15;
            cp16(smem_u32(B + o * ROWB + j * 16), WB + o * 256 + j * 16);
        }
        #pragma unroll
        for (int it = 0; it < 8; it++) {
            int id = tid + it * 256;
            int m = id >> 4, j = id & 15;
            cp16(smem_u32(A + m * ROWB + j * 16),
                 (const char*)g_xh + (size_t)s_src[0][m] * 256 + j * 16);
        }
        CP_COMMIT();
    }

    int buf = 0;
    for (int t = t0; t < t1; t++) {
        CP_WAIT0();
        __syncthreads();               // A(t), B(r) resident; meta[buf] visible

        bool hasNext = (t + 1 < t1);
        int rn = r;
        if (hasNext) { while (g_tstart[rn + 1] <= t + 1) rn++; }

        // meta prefetch for next tile into registers (hidden by mainloop)
        int m_src = 0, m_dinv = -1; float m_nrm = 0.f;
        if (hasNext && tid < TILE_M) {
            if (rn < RR) {
                int ebase = g_estart[rn] + (t + 1 - g_tstart[rn]) * TILE_M;
                int cnt = g_estart[rn + 1] - ebase; if (cnt > TILE_M) cnt = TILE_M;
                if (tid < cnt) {
                    int e = g_perm[ebase + tid];
                    m_src = src[e]; m_nrm = norm[e]; m_dinv = g_dinv[e];
                }
            } else {
                int n = (t + 1 - g_tstart[RR]) * TILE_M + tid;
                if (n < NN) { m_src = n; m_nrm = 1.f; m_dinv = EE + n; }
            }
        }

        uint32_t acc[2][8][2];
        #pragma unroll
        for (int a = 0; a < 2; a++)
            #pragma unroll
            for (int b = 0; b < 8; b++) { acc[a][b][0] = 0u; acc[a][b][1] = 0u; }

        #pragma unroll
        for (int s = 0; s < 8; s++) KSTEP(s, aAddr);

        // publish next meta (other buffer; no reader until next sync)
        if (hasNext && tid < TILE_M) {
            s_src[buf ^ 1][tid] = m_src;
            s_nrm[buf ^ 1][tid] = m_nrm;
            s_dinv[buf ^ 1][tid] = m_dinv;
        }

        // epilogue: scale by norm in fp32, store half2 at dst-rank
        {
            int colBase = wn * 64 + (lane & 3) * 2;
            #pragma unroll
            for (int mt = 0; mt < 2; mt++) {
                int row0 = rm + mt * 16 + (lane >> 2);
                int d0 = s_dinv[buf][row0], d1 = s_dinv[buf][row0 + 8];
                float n0 = s_nrm[buf][row0], n1 = s_nrm[buf][row0 + 8];
                __half* p0 = (d0 >= 0) ? g_edge_out + (size_t)d0 * FOUT + colBase : (__half*)0;
                __half* p1 = (d1 >= 0) ? g_edge_out + (size_t)d1 * FOUT + colBase : (__half*)0;
                #pragma unroll
                for (int nt = 0; nt < 8; nt++) {
                    if (p0) {
                        uint32_t v = acc[mt][nt][0];
                        float2 f = __half22float2(*(__half2*)&v);
                        *(__half2*)(p0 + nt * 8) = __floats2half2_rn(f.x * n0, f.y * n0);
                    }
                    if (p1) {
                        uint32_t v = acc[mt][nt][1];
                        float2 f = __half22float2(*(__half2*)&v);
                        *(__half2*)(p1 + nt * 8) = __floats2half2_rn(f.x * n1, f.y * n1);
                    }
                }
            }
        }

        __syncthreads();               // all reads of A/B done; meta[buf^1] published

        if (hasNext) {
            if (rn != r) {
                const char* WB = (const char*)g_WT + (size_t)rn * 32768;
                #pragma unroll
                for (int it = 0; it < 8; it++) {
                    int id = tid + it * 256;
                    int o = id >> 4, j = id & 15;
                    cp16(smem_u32(B + o * ROWB + j * 16), WB + o * 256 + j * 16);
                }
                r = rn;
            }
            int nb = buf ^ 1;
            #pragma unroll
            for (int it = 0; it < 8; it++) {
                int id = tid + it * 256;
                int m = id >> 4, j = id & 15;
                cp16(smem_u32(A + m * ROWB + j * 16),
                     (const char*)g_xh + (size_t)s_src[nb][m] * 256 + j * 16);
            }
            CP_COMMIT();
        }
        buf ^= 1;
    }
}

// ---------------- K6: warp-per-node reduce (boff inline) + bias/relu + residual ---
__global__ __launch_bounds__(256) void k_reduce(const float* __restrict__ h_bias,
                                                const float* __restrict__ b_res) {
    __shared__ int sboff[20];
    int tid = threadIdx.x;
    if (tid < 20) sboff[tid] = g_bsum[tid];
    __syncthreads();
    if (tid == 0) {
        int run = 0;
        #pragma unroll
        for (int k = 0; k < 20; k++) { int v = sboff[k]; sboff[k] = run; run += v; }
    }
    __syncthreads();

    int n = (blockIdx.x << 3) + (tid >> 5);
    int lane = tid & 31;
    int h = lane >> 4;
    int c = lane & 15;

    int s = g_dstart[n] + sboff[n / 1000];
    int e = (n + 1 == NN) ? EE : g_dstart[n + 1] + sboff[(n + 1) / 1000];
    float2 a0 = make_float2(0.f, 0.f), a1 = a0, a2 = a0, a3 = a0;

    const uint4* base = (const uint4*)g_edge_out;
    for (int j = s + h; j < e; j += 2) {
        uint4 v = base[(size_t)j * 16 + c];
        float2 f;
        f = __half22float2(*(__half2*)&v.x); a0.x += f.x; a0.y += f.y;
        f = __half22float2(*(__half2*)&v.y); a1.x += f.x; a1.y += f.y;
        f = __half22float2(*(__half2*)&v.z); a2.x += f.x; a2.y += f.y;
        f = __half22float2(*(__half2*)&v.w); a3.x += f.x; a3.y += f.y;
    }
    a0.x += __shfl_down_sync(0xffffffffu, a0.x, 16);
    a0.y += __shfl_down_sync(0xffffffffu, a0.y, 16);
    a1.x += __shfl_down_sync(0xffffffffu, a1.x, 16);
    a1.y += __shfl_down_sync(0xffffffffu, a1.y, 16);
    a2.x += __shfl_down_sync(0xffffffffu, a2.x, 16);
    a2.y += __shfl_down_sync(0xffffffffu, a2.y, 16);
    a3.x += __shfl_down_sync(0xffffffffu, a3.x, 16);
    a3.y += __shfl_down_sync(0xffffffffu, a3.y, 16);

    if (h == 0) {
        const float4* bia = (const float4*)h_bias;
        float4 b0 = __ldg(&bia[c * 2]), b1 = __ldg(&bia[c * 2 + 1]);
        uint4 rv = base[(size_t)(EE + n) * 16 + c];
        float2 rf0 = __half22float2(*(__half2*)&rv.x);
        float2 rf1 = __half22float2(*(__half2*)&rv.y);
        float2 rf2 = __half22float2(*(__half2*)&rv.z);
        float2 rf3 = __half22float2(*(__half2*)&rv.w);
        const float4* brp = (const float4*)b_res;
        float4 br0 = __ldg(&brp[c * 2]), br1 = __ldg(&brp[c * 2 + 1]);

        float4 o0, o1;
        o0.x = fmaxf(a0.x + b0.x, 0.f) + fmaxf(rf0.x + br0.x, 0.f);
        o0.y = fmaxf(a0.y + b0.y, 0.f) + fmaxf(rf0.y + br0.y, 0.f);
        o0.z = fmaxf(a1.x + b0.z, 0.f) + fmaxf(rf1.x + br0.z, 0.f);
        o0.w = fmaxf(a1.y + b0.w, 0.f) + fmaxf(rf1.y + br0.w, 0.f);
        o1.x = fmaxf(a2.x + b1.x, 0.f) + fmaxf(rf2.x + br1.x, 0.f);
        o1.y = fmaxf(a2.y + b1.y, 0.f) + fmaxf(rf2.y + br1.y, 0.f);
        o1.z = fmaxf(a3.x + b1.z, 0.f) + fmaxf(rf3.x + br1.z, 0.f);
        o1.w = fmaxf(a3.y + b1.w, 0.f) + fmaxf(rf3.y + br1.w, 0.f);
        ((float4*)g_h)[(size_t)n * 32 + c * 2]     = o0;
        ((float4*)g_h)[(size_t)n * 32 + c * 2 + 1] = o1;
    }
}

// ---------------- K7: BN partial sums ----------------------------------------------
__global__ __launch_bounds__(128) void k_bnsum() {
    int b = blockIdx.x, o = threadIdx.x;
    float s = 0.f, sq = 0.f;
    int r0 = b * (NN / NBN), r1 = r0 + (NN / NBN);
    for (int n = r0; n < r1; n++) {
        float v = g_h[(size_t)n * FOUT + o];
        s += v; sq += v * v;
    }
    g_psum[b * FOUT + o] = s;
    g_psq[b * FOUT + o] = sq;
}

// ---------------- K8: BN finalize folded into output apply -------------------------
__global__ __launch_bounds__(256) void k_out(float* __restrict__ out,
                                             const float* __restrict__ gamma,
                                             const float* __restrict__ beta) {
    __shared__ float ssc[FOUT], ssh[FOUT];
    __shared__ float t0s[FOUT], t1s[FOUT];
    int tid = threadIdx.x;
    {
        int o = tid & 127, hf = tid >> 7;
        float s = 0.f, sq = 0.f;
        int b0 = hf * (NBN / 2), b1 = b0 + (NBN / 2);
        for (int b = b0; b < b1; b++) {
            s  += g_psum[b * FOUT + o];
            sq += g_psq[b * FOUT + o];
        }
        if (hf == 1) { t0s[o] = s; t1s[o] = sq; }
        __syncthreads();
        if (hf == 0) {
            float S = s + t0s[o], SQ = sq + t1s[o];
            float mean = S / (float)NN;
            float var = SQ / (float)NN - mean * mean;
            float sc = __ldg(&gamma[o]) * rsqrtf(var + 1e-5f);
            ssc[o] = sc;
            ssh[o] = __ldg(&beta[o]) - mean * sc;
        }
        __syncthreads();
    }
    for (int i = blockIdx.x * 256 + tid; i < NN * FOUT / 4; i += gridDim.x * 256) {
        float4 v = ((const float4*)g_h)[i];
        int c4 = i & 31;
        float4 sc = *(float4*)&ssc[c4 * 4];
        float4 sh = *(float4*)&ssh[c4 * 4];
        float4 o;
        o.x = v.x * sc.x + sh.x;
        o.y = v.y * sc.y + sh.y;
        o.z = v.z * sc.z + sh.z;
        o.w = v.w * sc.w + sh.w;
        ((float4*)out)[i] = o;
    }
}

// ---------------- launch -------------------------------------------------------------
extern "C" void kernel_launch(void* const* d_in, const int* in_sizes, int n_in,
                              void* d_out, int out_size) {
    const float* node_feats = (const float*)d_in[0];
    const int*   src        = (const int*)d_in[1];
    const int*   dst        = (const int*)d_in[2];
    const int*   etype      = (const int*)d_in[3];
    const float* norm       = (const float*)d_in[4];
    const float* basis      = (const float*)d_in[5];
    const float* comp       = (const float*)d_in[6];
    const float* h_bias     = (const float*)d_in[7];
    const float* W_res      = (const float*)d_in[8];
    const float* b_res      = (const float*)d_in[9];
    const float* gamma      = (const float*)d_in[10];
    const float* beta       = (const float*)d_in[11];
    float* out = (float*)d_out;

    const int DSMEM   = 2 * ATILE;                      // 69632 B -> 3 CTAs/SM
    const int KW_SMEM = (BB * FIN + RR * BB) * 4;       // 50180 B
    cudaFuncSetAttribute(k_gemm, cudaFuncAttributeMaxDynamicSharedMemorySize, DSMEM);
    cudaFuncSetAttribute(k_w, cudaFuncAttributeMaxDynamicSharedMemorySize, KW_SMEM);

    k_w<<<FIN, 128, KW_SMEM>>>(basis, comp);
    k_pre<<<(NN * FIN / 2 + 255) / 256, 256>>>(node_feats, etype, dst, W_res);
    k_scan1<<<21, 1024>>>();
    k_scatter<<<(EE + 255) / 256, 256>>>(etype, dst);
    k_gemm<<<GEMM_GRID, 256, DSMEM>>>(src, norm);
    k_reduce<<<NN / 8, 256>>>(h_bias, b_res);
    k_bnsum<<<NBN, 128>>>();
    k_out<<<160, 256>>>(out, gamma, beta);
    (void)in_sizes; (void)n_in; (void)out_size;
}

// round 16
// speedup vs baseline: 1.2168x; 1.0082x over previous
#include <cuda_runtime.h>
#include <cuda_fp16.h>
#include <stdint.h>

// Problem constants
#define NN   20000
#define EE   640000
#define FIN  128
#define FOUT 128
#define RR   65
#define BB   65
#define TILE_M 128
#define NBN  200

#define ROWB 272                  // bytes per smem tile row (136 halves, padded)
#define ATILE (128 * ROWB)        // 34816 B
#define GEMM_GRID 444             // 3 CTAs per SM
#define NTSYN ((NN + TILE_M - 1) / TILE_M)   // synthetic residual tiles (157)

// ---------------- scratch (__device__ globals) ------------------------------
__device__ __align__(16) __half g_WT[(size_t)(RR + 1) * FOUT * FIN]; // slot RR = W_res
__device__ __align__(16) __half g_xh[(size_t)NN * FIN];
__device__ int   g_cnt[RR];
__device__ int   g_rcur[RR];
__device__ int   g_estart[RR + 1];
__device__ int   g_tstart[RR + 2];
__device__ int   g_perm[EE];
__device__ int   g_dcnt[NN];
__device__ int   g_dcur[NN];
__device__ int   g_dstart[NN];                   // LOCAL exclusive (per 1000-chunk)
__device__ int   g_bsum[20];
__device__ int   g_dinv[EE];                     // edge -> dst-sorted rank
__device__ __align__(16) __half g_edge_out[(size_t)(EE + NN) * FOUT];
__device__ float g_h[(size_t)NN * FOUT];
__device__ float g_psum[NBN * FOUT];
__device__ float g_psq[NBN * FOUT];

// ---------------- helpers ----------------------------------------------------
__device__ __forceinline__ uint32_t smem_u32(const void* p) {
    uint32_t a;
    asm("{ .reg .u64 t; cvta.to.shared.u64 t, %1; cvt.u32.u64 %0, t; }"
        : "=r"(a) : "l"(p));
    return a;
}

__device__ __forceinline__ void ldsm_x4(uint32_t addr, uint32_t& r0, uint32_t& r1,
                                        uint32_t& r2, uint32_t& r3) {
    asm volatile("ldmatrix.sync.aligned.m8n8.x4.shared.b16 {%0,%1,%2,%3}, [%4];"
                 : "=r"(r0), "=r"(r1), "=r"(r2), "=r"(r3) : "r"(addr));
}

__device__ __forceinline__ void mma16816h(uint32_t* c, const uint32_t* a,
                                          uint32_t b0, uint32_t b1) {
    asm volatile(
        "mma.sync.aligned.m16n8k16.row.col.f16.f16.f16.f16 "
        "{%0,%1}, {%2,%3,%4,%5}, {%6,%7}, {%0,%1};"
        : "+r"(c[0]), "+r"(c[1])
        : "r"(a[0]), "r"(a[1]), "r"(a[2]), "r"(a[3]), "r"(b0), "r"(b1));
}

__device__ __forceinline__ void cp16(uint32_t dst, const void* src) {
    asm volatile("cp.async.cg.shared.global [%0], [%1], 16;"
                 :: "r"(dst), "l"(src) : "memory");
}
#define CP_COMMIT() asm volatile("cp.async.commit_group;" ::: "memory")
#define CP_WAIT0()  asm volatile("cp.async.wait_group 0;" ::: "memory")

// ---------------- K1: WT fp16 (+ zero counters) ---------------------------------
__global__ __launch_bounds__(128) void k_w(const float* __restrict__ basis,
                                           const float* __restrict__ comp) {
    extern __shared__ float swm[];
    float* sb = swm;              // [BB][FIN]
    float* sc = swm + BB * FIN;   // [RR*BB]

    int i = blockIdx.x, o = threadIdx.x;

    int gi = blockIdx.x * 128 + o;
    for (int z = gi; z < NN; z += FIN * 128) { g_dcnt[z] = 0; g_dcur[z] = 0; }
    if (gi < RR) { g_cnt[gi] = 0; g_rcur[gi] = 0; }

    for (int b = 0; b < BB; b++)
        sb[b * FIN + o] = basis[(size_t)b * FIN * FOUT + (size_t)i * FOUT + o];
    for (int idx = o; idx < RR * BB; idx += 128)
        sc[idx] = comp[idx];
    __syncthreads();

    float acc[RR];
    #pragma unroll
    for (int r = 0; r < RR; r++) acc[r] = 0.f;

    for (int b = 0; b < BB; b++) {
        float sv = sb[b * FIN + o];
        #pragma unroll
        for (int r = 0; r < RR; r++)
            acc[r] += sc[r * BB + b] * sv;
    }

    #pragma unroll 1
    for (int r = 0; r < RR; r++)
        g_WT[((size_t)r * FOUT + o) * FIN + i] = __float2half(acc[r]);
}

// ---------------- K2: merged preprocessing ---------------------------------------
__global__ void k_pre(const float* __restrict__ x,
                      const int* __restrict__ etype,
                      const int* __restrict__ dst,
                      const float* __restrict__ Wres) {
    __shared__ int sh[RR];
    int tid = threadIdx.x;
    int gb = blockIdx.x;
    int i = gb * 256 + tid;

    if (i < NN * FIN / 2) {
        float2 v = ((const float2*)x)[i];
        ((__half2*)g_xh)[i] = __floats2half2_rn(v.x, v.y);
    }
    if (i < FIN * FOUT) {
        int k = i >> 7, o = i & 127;
        g_WT[((size_t)RR * FOUT + o) * FIN + k] = __float2half(Wres[i]);
    }
    if (gb < (EE + 255) / 256) {
        if (tid < RR) sh[tid] = 0;
        __syncthreads();
        if (i < EE) {
            atomicAdd(&sh[etype[i]], 1);
            atomicAdd(&g_dcnt[dst[i]], 1);
        }
        __syncthreads();
        if (tid < RR && sh[tid]) atomicAdd(&g_cnt[tid], sh[tid]);
    }
}

// ---------------- K3: local dst scans (blocks 0-19) + relation scan (block 20) ----
__global__ __launch_bounds__(1024) void k_scan1() {
    if (blockIdx.x == 20) {
        if (threadIdx.x == 0) {
            int es = 0, ts = 0;
            for (int r = 0; r < RR; r++) {
                g_estart[r] = es; g_tstart[r] = ts;
                es += g_cnt[r];
                ts += (g_cnt[r] + TILE_M - 1) / TILE_M;
            }
            g_estart[RR] = es;
            g_tstart[RR] = ts;
            g_tstart[RR + 1] = ts + NTSYN;
        }
        return;
    }
    __shared__ int sa[1024], sb2[1024];
    int t = threadIdx.x;
    int g = blockIdx.x * 1000;
    int v = (t < 1000) ? g_dcnt[g + t] : 0;
    sa[t] = v;
    __syncthreads();
    int* in = sa; int* out = sb2;
    #pragma unroll
    for (int off = 1; off < 1024; off <<= 1) {
        out[t] = in[t] + ((t >= off) ? in[t - off] : 0);
        __syncthreads();
        int* tmp = in; in = out; out = tmp;
    }
    if (t < 1000) g_dstart[g + t] = in[t] - v;      // local exclusive
    if (t == 999) g_bsum[blockIdx.x] = in[t];       // block total
}

// ---------------- K4: scatter, 4 edges/thread (MLP on atomic chains) --------------
__global__ __launch_bounds__(256) void k_scatter(const int* __restrict__ etype,
                                                 const int* __restrict__ dst) {
    __shared__ int s_cnt[RR], s_base[RR], sboff[20];
    int tid = threadIdx.x;
    if (tid < RR) s_cnt[tid] = 0;
    if (tid >= 64 && tid < 84) sboff[tid - 64] = g_bsum[tid - 64];
    __syncthreads();
    if (tid == 0) {
        int run = 0;
        #pragma unroll
        for (int k = 0; k < 20; k++) { int v = sboff[k]; sboff[k] = run; run += v; }
    }
    __syncthreads();

    int e0 = blockIdx.x * 1024 + tid * 4;           // EE % 1024 == 0, no bounds
    int4 rv4 = __ldg(&((const int4*)etype)[e0 >> 2]);
    int4 dv4 = __ldg(&((const int4*)dst)[e0 >> 2]);
    int rv[4] = { rv4.x, rv4.y, rv4.z, rv4.w };
    int dvv[4] = { dv4.x, dv4.y, dv4.z, dv4.w };
    int lr[4];
    #pragma unroll
    for (int q = 0; q < 4; q++)
        lr[q] = atomicAdd(&s_cnt[rv[q]], 1);
    __syncthreads();
    if (tid < RR && s_cnt[tid] > 0) s_base[tid] = atomicAdd(&g_rcur[tid], s_cnt[tid]);
    __syncthreads();
    #pragma unroll
    for (int q = 0; q < 4; q++) {
        int e = e0 + q;
        g_perm[g_estart[rv[q]] + s_base[rv[q]] + lr[q]] = e;
        int d = dvv[q];
        g_dinv[e] = g_dstart[d] + sboff[d / 1000] + atomicAdd(&g_dcur[d], 1);
    }
}

// single-product k-step, fp16 accumulators
#define KSTEP(S, aA) do { \
    uint32_t ka = (aA) + (S) * 32; \
    uint32_t a0[4], a1[4]; \
    ldsm_x4(ka,             a0[0], a0[1], a0[2], a0[3]); \
    ldsm_x4(ka + 16 * ROWB, a1[0], a1[1], a1[2], a1[3]); \
    uint32_t kb = bAddr + (S) * 32; \
    _Pragma("unroll") \
    for (int pr = 0; pr < 4; pr++) { \
        uint32_t b0, b1, b2, b3; \
        ldsm_x4(kb + pr * 16 * ROWB, b0, b1, b2, b3); \
        int nt = pr * 2; \
        mma16816h(acc[0][nt],     a0, b0, b1); \
        mma16816h(acc[1][nt],     a1, b0, b1); \
        mma16816h(acc[0][nt + 1], a0, b2, b3); \
        mma16816h(acc[1][nt + 1], a1, b2, b3); \
    } \
} while (0)

// ---------------- K5: persistent HMMA GEMM, 3 CTAs/SM, epilogue-covered prefetch --
__global__ __launch_bounds__(256, 3) void k_gemm(const int* __restrict__ src,
                                                 const float* __restrict__ norm) {
    extern __shared__ char dsm[];
    __shared__ int   s_src[2][TILE_M];
    __shared__ float s_nrm[2][TILE_M];
    __shared__ int   s_dinv[2][TILE_M];

    char* A = dsm;
    char* B = dsm + ATILE;

    int tid = threadIdx.x;
    int T = g_tstart[RR + 1];
    int per = (T + GEMM_GRID - 1) / GEMM_GRID;
    int t0 = blockIdx.x * per;
    int t1 = t0 + per; if (t1 > T) t1 = T;
    if (t0 >= t1) return;

    int lane = tid & 31, w = tid >> 5;
    int wm = w & 3, wn = w >> 2;
    int rm = wm * 32;
    uint32_t aLane = (uint32_t)((rm + (lane & 15)) * ROWB + ((lane >> 4) << 4));
    uint32_t bLane = (uint32_t)((wn * 64 + ((lane >> 4) << 3) + (lane & 7)) * ROWB
                                + (((lane >> 3) & 1) << 4));
    uint32_t aAddr = smem_u32(A) + aLane;
    uint32_t bAddr = smem_u32(B) + bLane;

    int r = 0;
    while (g_tstart[r + 1] <= t0) r++;

    // ---- meta for tile t0 (buf 0) ----
    if (tid < TILE_M) {
        int sv = 0, dv = -1; float nm = 0.f;
        if (r < RR) {
            int ebase = g_estart[r] + (t0 - g_tstart[r]) * TILE_M;
            int cnt = g_estart[r + 1] - ebase; if (cnt > TILE_M) cnt = TILE_M;
            if (tid < cnt) {
                int e = g_perm[ebase + tid];
                sv = src[e]; nm = norm[e]; dv = g_dinv[e];
            }
        } else {
            int n = (t0 - g_tstart[RR]) * TILE_M + tid;
            if (n < NN) { sv = n; nm = 1.f; dv = EE + n; }
        }
        s_src[0][tid] = sv; s_nrm[0][tid] = nm; s_dinv[0][tid] = dv;
    }
    __syncthreads();

    // ---- B fill for first relation + A fill for t0 ----
    {
        const char* WB = (const char*)g_WT + (size_t)r * 32768;
        #pragma unroll
        for (int it = 0; it < 8; it++) {
            int id = tid + it * 256;
            int o = id >> 4, j = id & 15;
            cp16(smem_u32(B + o * ROWB + j * 16), WB + o * 256 + j * 16);
        }
        #pragma unroll
        for (int it = 0; it < 8; it++) {
            int id = tid + it * 256;
            int m = id >> 4, j = id & 15;
            cp16(smem_u32(A + m * ROWB + j * 16),
                 (const char*)g_xh + (size_t)s_src[0][m] * 256 + j * 16);
        }
        CP_COMMIT();
    }

    int buf = 0;
    for (int t = t0; t < t1; t++) {
        CP_WAIT0();
        __syncthreads();               // A(t), B(r) resident; meta[buf] visible

        bool hasNext = (t + 1 < t1);
        int rn = r;
        if (hasNext) { while (g_tstart[rn + 1] <= t + 1) rn++; }

        // meta prefetch for next tile into registers (hidden by mainloop)
        int m_src = 0, m_dinv = -1; float m_nrm = 0.f;
        if (hasNext && tid < TILE_M) {
            if (rn < RR) {
                int ebase = g_estart[rn] + (t + 1 - g_tstart[rn]) * TILE_M;
                int cnt = g_estart[rn + 1] - ebase; if (cnt > TILE_M) cnt = TILE_M;
                if (tid < cnt) {
                    int e = g_perm[ebase + tid];
                    m_src = src[e]; m_nrm = norm[e]; m_dinv = g_dinv[e];
                }
            } else {
                int n = (t + 1 - g_tstart[RR]) * TILE_M + tid;
                if (n < NN) { m_src = n; m_nrm = 1.f; m_dinv = EE + n; }
            }
        }

        uint32_t acc[2][8][2];
        #pragma unroll
        for (int a = 0; a < 2; a++)
            #pragma unroll
            for (int b = 0; b < 8; b++) { acc[a][b][0] = 0u; acc[a][b][1] = 0u; }

        #pragma unroll
        for (int s = 0; s < 8; s++) KSTEP(s, aAddr);

        // publish next meta
        if (hasNext && tid < TILE_M) {
            s_src[buf ^ 1][tid] = m_src;
            s_nrm[buf ^ 1][tid] = m_nrm;
            s_dinv[buf ^ 1][tid] = m_dinv;
        }
        __syncthreads();               // A/B reads done; meta[buf^1] published

        // issue next tile's fills BEFORE the epilogue: the store drain covers
        // the cp.async L2 latency.
        if (hasNext) {
            if (rn != r) {
                const char* WB = (const char*)g_WT + (size_t)rn * 32768;
                #pragma unroll
                for (int it = 0; it < 8; it++) {
                    int id = tid + it * 256;
                    int o = id >> 4, j = id & 15;
                    cp16(smem_u32(B + o * ROWB + j * 16), WB + o * 256 + j * 16);
                }
                r = rn;
            }
            int nb = buf ^ 1;
            #pragma unroll
            for (int it = 0; it < 8; it++) {
                int id = tid + it * 256;
                int m = id >> 4, j = id & 15;
                cp16(smem_u32(A + m * ROWB + j * 16),
                     (const char*)g_xh + (size_t)s_src[nb][m] * 256 + j * 16);
            }
            CP_COMMIT();
        }

        // epilogue: scale by norm in fp32, store half2 at dst-rank (overlaps fill)
        {
            int colBase = wn * 64 + (lane & 3) * 2;
            #pragma unroll
            for (int mt = 0; mt < 2; mt++) {
                int row0 = rm + mt * 16 + (lane >> 2);
                int d0 = s_dinv[buf][row0], d1 = s_dinv[buf][row0 + 8];
                float n0 = s_nrm[buf][row0], n1 = s_nrm[buf][row0 + 8];
                __half* p0 = (d0 >= 0) ? g_edge_out + (size_t)d0 * FOUT + colBase : (__half*)0;
                __half* p1 = (d1 >= 0) ? g_edge_out + (size_t)d1 * FOUT + colBase : (__half*)0;
                #pragma unroll
                for (int nt = 0; nt < 8; nt++) {
                    if (p0) {
                        uint32_t v = acc[mt][nt][0];
                        float2 f = __half22float2(*(__half2*)&v);
                        *(__half2*)(p0 + nt * 8) = __floats2half2_rn(f.x * n0, f.y * n0);
                    }
                    if (p1) {
                        uint32_t v = acc[mt][nt][1];
                        float2 f = __half22float2(*(__half2*)&v);
                        *(__half2*)(p1 + nt * 8) = __floats2half2_rn(f.x * n1, f.y * n1);
                    }
                }
            }
        }
        buf ^= 1;
    }
}

// ---------------- K6: warp-per-node reduce (boff inline) + bias/relu + residual ---
__global__ __launch_bounds__(256) void k_reduce(const float* __restrict__ h_bias,
                                                const float* __restrict__ b_res) {
    __shared__ int sboff[20];
    int tid = threadIdx.x;
    if (tid < 20) sboff[tid] = g_bsum[tid];
    __syncthreads();
    if (tid == 0) {
        int run = 0;
        #pragma unroll
        for (int k = 0; k < 20; k++) { int v = sboff[k]; sboff[k] = run; run += v; }
    }
    __syncthreads();

    int n = (blockIdx.x << 3) + (tid >> 5);
    int lane = tid & 31;
    int h = lane >> 4;
    int c = lane & 15;

    int s = g_dstart[n] + sboff[n / 1000];
    int e = (n + 1 == NN) ? EE : g_dstart[n + 1] + sboff[(n + 1) / 1000];
    float2 a0 = make_float2(0.f, 0.f), a1 = a0, a2 = a0, a3 = a0;

    const uint4* base = (const uint4*)g_edge_out;
    for (int j = s + h; j < e; j += 2) {
        uint4 v = base[(size_t)j * 16 + c];
        float2 f;
        f = __half22float2(*(__half2*)&v.x); a0.x += f.x; a0.y += f.y;
        f = __half22float2(*(__half2*)&v.y); a1.x += f.x; a1.y += f.y;
        f = __half22float2(*(__half2*)&v.z); a2.x += f.x; a2.y += f.y;
        f = __half22float2(*(__half2*)&v.w); a3.x += f.x; a3.y += f.y;
    }
    a0.x += __shfl_down_sync(0xffffffffu, a0.x, 16);
    a0.y += __shfl_down_sync(0xffffffffu, a0.y, 16);
    a1.x += __shfl_down_sync(0xffffffffu, a1.x, 16);
    a1.y += __shfl_down_sync(0xffffffffu, a1.y, 16);
    a2.x += __shfl_down_sync(0xffffffffu, a2.x, 16);
    a2.y += __shfl_down_sync(0xffffffffu, a2.y, 16);
    a3.x += __shfl_down_sync(0xffffffffu, a3.x, 16);
    a3.y += __shfl_down_sync(0xffffffffu, a3.y, 16);

    if (h == 0) {
        const float4* bia = (const float4*)h_bias;
        float4 b0 = __ldg(&bia[c * 2]), b1 = __ldg(&bia[c * 2 + 1]);
        uint4 rv = base[(size_t)(EE + n) * 16 + c];
        float2 rf0 = __half22float2(*(__half2*)&rv.x);
        float2 rf1 = __half22float2(*(__half2*)&rv.y);
        float2 rf2 = __half22float2(*(__half2*)&rv.z);
        float2 rf3 = __half22float2(*(__half2*)&rv.w);
        const float4* brp = (const float4*)b_res;
        float4 br0 = __ldg(&brp[c * 2]), br1 = __ldg(&brp[c * 2 + 1]);

        float4 o0, o1;
        o0.x = fmaxf(a0.x + b0.x, 0.f) + fmaxf(rf0.x + br0.x, 0.f);
        o0.y = fmaxf(a0.y + b0.y, 0.f) + fmaxf(rf0.y + br0.y, 0.f);
        o0.z = fmaxf(a1.x + b0.z, 0.f) + fmaxf(rf1.x + br0.z, 0.f);
        o0.w = fmaxf(a1.y + b0.w, 0.f) + fmaxf(rf1.y + br0.w, 0.f);
        o1.x = fmaxf(a2.x + b1.x, 0.f) + fmaxf(rf2.x + br1.x, 0.f);
        o1.y = fmaxf(a2.y + b1.y, 0.f) + fmaxf(rf2.y + br1.y, 0.f);
        o1.z = fmaxf(a3.x + b1.z, 0.f) + fmaxf(rf3.x + br1.z, 0.f);
        o1.w = fmaxf(a3.y + b1.w, 0.f) + fmaxf(rf3.y + br1.w, 0.f);
        ((float4*)g_h)[(size_t)n * 32 + c * 2]     = o0;
        ((float4*)g_h)[(size_t)n * 32 + c * 2 + 1] = o1;
    }
}

// ---------------- K7: BN partial sums ----------------------------------------------
__global__ __launch_bounds__(128) void k_bnsum() {
    int b = blockIdx.x, o = threadIdx.x;
    float s = 0.f, sq = 0.f;
    int r0 = b * (NN / NBN), r1 = r0 + (NN / NBN);
    for (int n = r0; n < r1; n++) {
        float v = g_h[(size_t)n * FOUT + o];
        s += v; sq += v * v;
    }
    g_psum[b * FOUT + o] = s;
    g_psq[b * FOUT + o] = sq;
}

// ---------------- K8: BN finalize folded into output apply -------------------------
__global__ __launch_bounds__(256) void k_out(float* __restrict__ out,
                                             const float* __restrict__ gamma,
                                             const float* __restrict__ beta) {
    __shared__ float ssc[FOUT], ssh[FOUT];
    __shared__ float t0s[FOUT], t1s[FOUT];
    int tid = threadIdx.x;
    {
        int o = tid & 127, hf = tid >> 7;
        float s = 0.f, sq = 0.f;
        int b0 = hf * (NBN / 2), b1 = b0 + (NBN / 2);
        for (int b = b0; b < b1; b++) {
            s  += g_psum[b * FOUT + o];
            sq += g_psq[b * FOUT + o];
        }
        if (hf == 1) { t0s[o] = s; t1s[o] = sq; }
        __syncthreads();
        if (hf == 0) {
            float S = s + t0s[o], SQ = sq + t1s[o];
            float mean = S / (float)NN;
            float var = SQ / (float)NN - mean * mean;
            float sc = __ldg(&gamma[o]) * rsqrtf(var + 1e-5f);
            ssc[o] = sc;
            ssh[o] = __ldg(&beta[o]) - mean * sc;
        }
        __syncthreads();
    }
    for (int i = blockIdx.x * 256 + tid; i < NN * FOUT / 4; i += gridDim.x * 256) {
        float4 v = ((const float4*)g_h)[i];
        int c4 = i & 31;
        float4 sc = *(float4*)&ssc[c4 * 4];
        float4 sh = *(float4*)&ssh[c4 * 4];
        float4 o;
        o.x = v.x * sc.x + sh.x;
        o.y = v.y * sc.y + sh.y;
        o.z = v.z * sc.z + sh.z;
        o.w = v.w * sc.w + sh.w;
        ((float4*)out)[i] = o;
    }
}

// ---------------- launch -------------------------------------------------------------
extern "C" void kernel_launch(void* const* d_in, const int* in_sizes, int n_in,
                              void* d_out, int out_size) {
    const float* node_feats = (const float*)d_in[0];
    const int*   src        = (const int*)d_in[1];
    const int*   dst        = (const int*)d_in[2];
    const int*   etype      = (const int*)d_in[3];
    const float* norm       = (const float*)d_in[4];
    const float* basis      = (const float*)d_in[5];
    const float* comp       = (const float*)d_in[6];
    const float* h_bias     = (const float*)d_in[7];
    const float* W_res      = (const float*)d_in[8];
    const float* b_res      = (const float*)d_in[9];
    const float* gamma      = (const float*)d_in[10];
    const float* beta       = (const float*)d_in[11];
    float* out = (float*)d_out;

    const int DSMEM   = 2 * ATILE;                      // 69632 B -> 3 CTAs/SM
    const int KW_SMEM = (BB * FIN + RR * BB) * 4;       // 50180 B
    cudaFuncSetAttribute(k_gemm, cudaFuncAttributeMaxDynamicSharedMemorySize, DSMEM);
    cudaFuncSetAttribute(k_w, cudaFuncAttributeMaxDynamicSharedMemorySize, KW_SMEM);

    k_w<<<FIN, 128, KW_SMEM>>>(basis, comp);
    k_pre<<<(NN * FIN / 2 + 255) / 256, 256>>>(node_feats, etype, dst, W_res);
    k_scan1<<<21, 1024>>>();
    k_scatter<<<EE / 1024, 256>>>(etype, dst);
    k_gemm<<<GEMM_GRID, 256, DSMEM>>>(src, norm);
    k_reduce<<<NN / 8, 256>>>(h_bias, b_res);
    k_bnsum<<<NBN, 128>>>();
    k_out<<<160, 256>>>(out, gamma, beta);
    (void)in_sizes; (void)n_in; (void)out_size;
}